// round 4
// baseline (speedup 1.0000x reference)
#include <cuda_runtime.h>
#include <math.h>

#define BDIM 8
#define SDIM 2048
#define TDIM 128
#define NTOK (BDIM * SDIM)

#define BM 64
#define BK 32
#define PAD_N 68
#define PAD_T 132
#define SMEM_FLOATS (2 * 128 * PAD_N + 2 * BK * PAD_T)
#define SMEM_BYTES (SMEM_FLOATS * 4)

__device__ float g_base[TDIM];

// ---------------------------------------------------------------------------
// Kernel 1: base[t] = sum(w_red) * tanh(b_comp[t]) + b_red[0]
// ---------------------------------------------------------------------------
__global__ void base_kernel(const float* __restrict__ b_comp,
                            const float* __restrict__ w_red,
                            const float* __restrict__ b_red) {
    __shared__ float red[128];
    int tid = threadIdx.x;
    float s = 0.f;
    for (int i = tid; i < SDIM; i += 128) s += w_red[i];
    red[tid] = s;
    __syncthreads();
    for (int o = 64; o > 0; o >>= 1) {
        if (tid < o) red[tid] += red[tid + o];
        __syncthreads();
    }
    float sw = red[0];
    g_base[tid] = sw * tanhf(b_comp[tid]) + b_red[0];
}

// ---------------------------------------------------------------------------
// Kernel 2: out[b,i,t] = base[t]   (scatter deltas added later via atomics)
// ---------------------------------------------------------------------------
__global__ void init_kernel(float* __restrict__ out) {
    int i = blockIdx.x * blockDim.x + threadIdx.x;   // over NTOK*TDIM/4 float4s
    int t4 = (i & 31) << 2;                          // 32 float4 per T-row
    float4 v = make_float4(g_base[t4], g_base[t4 + 1], g_base[t4 + 2], g_base[t4 + 3]);
    reinterpret_cast<float4*>(out)[i] = v;
}

// ---------------------------------------------------------------------------
// Kernel 3: main bilinear GEMM + tanh epilogue + scatter-add
// C[n,t] = sum_{p,q} token[n,p] * h[n,q] * W[t,p,q],  h = tanh(token)
// Block: 64 tokens x 128 t, 128 threads, 8x8 register tile each.
// K = 16384 = (p,q), streamed as 512 chunks of 32 q (p = chunk>>2).
// ---------------------------------------------------------------------------
__global__ __launch_bounds__(128, 2)
void bilinear_kernel(const float* __restrict__ tok,
                     const float* __restrict__ W,
                     const int* __restrict__ heads,
                     const float* __restrict__ w_red,
                     const float* __restrict__ b_comp,
                     float* __restrict__ out)
{
    extern __shared__ float smem[];
    float* sh_t = smem;                     // [128 p][PAD_N]  token (transposed)
    float* sh_h = smem + 128 * PAD_N;       // [128 q][PAD_N]  tanh(token)
    float* sh_w = smem + 2 * 128 * PAD_N;   // [2][BK q][PAD_T t]

    const int tid = threadIdx.x;
    const int nbase = blockIdx.x * BM;
    const int ng = tid >> 4;                // 0..7  -> 8 tokens
    const int tg = tid & 15;                // 0..15 -> 8 t
    const int n0 = ng << 3;
    const int t0 = tg << 3;

    // Load token tile, build both transposed copies (token and tanh(token)).
    #pragma unroll 4
    for (int e = tid; e < BM * 128; e += 128) {
        int n = e >> 7;
        int p = e & 127;
        float v = tok[(nbase + n) * 128 + p];
        sh_t[p * PAD_N + n] = v;
        sh_h[p * PAD_N + n] = tanhf(v);
    }

    const float4* W4 = reinterpret_cast<const float4*>(W);
    float4 pre[8];

    // Prologue: fetch chunk 0 and stage into buffer 0.
    #pragma unroll
    for (int i = 0; i < 8; i++) {
        int e4 = tid + i * 128;
        int t = e4 >> 3, qw = e4 & 7;
        pre[i] = W4[t * 4096 + qw];          // p=0, qc=0
    }
    #pragma unroll
    for (int i = 0; i < 8; i++) {
        int e4 = tid + i * 128;
        int t = e4 >> 3, qw = e4 & 7;
        sh_w[(qw * 4 + 0) * PAD_T + t] = pre[i].x;
        sh_w[(qw * 4 + 1) * PAD_T + t] = pre[i].y;
        sh_w[(qw * 4 + 2) * PAD_T + t] = pre[i].z;
        sh_w[(qw * 4 + 3) * PAD_T + t] = pre[i].w;
    }
    __syncthreads();

    float acc[8][8];
    #pragma unroll
    for (int i = 0; i < 8; i++)
        #pragma unroll
        for (int j = 0; j < 8; j++) acc[i][j] = 0.f;

    for (int kc = 0; kc < 512; kc++) {
        const int buf = kc & 1;

        // Prefetch next W chunk into registers (overlaps with compute below).
        if (kc + 1 < 512) {
            int pn = (kc + 1) >> 2, qcn = (kc + 1) & 3;
            #pragma unroll
            for (int i = 0; i < 8; i++) {
                int e4 = tid + i * 128;
                int t = e4 >> 3, qw = e4 & 7;
                pre[i] = W4[t * 4096 + pn * 32 + qcn * 8 + qw];
            }
        }

        const int p = kc >> 2, qc = kc & 3;
        float a[8];
        {
            float4 a0 = *reinterpret_cast<const float4*>(&sh_t[p * PAD_N + n0]);
            float4 a1 = *reinterpret_cast<const float4*>(&sh_t[p * PAD_N + n0 + 4]);
            a[0] = a0.x; a[1] = a0.y; a[2] = a0.z; a[3] = a0.w;
            a[4] = a1.x; a[5] = a1.y; a[6] = a1.z; a[7] = a1.w;
        }
        const float* wbuf = sh_w + buf * BK * PAD_T;
        const float* hrow = sh_h + (qc * 32) * PAD_N;

        #pragma unroll 4
        for (int q = 0; q < 32; q++) {
            float4 h0 = *reinterpret_cast<const float4*>(&hrow[q * PAD_N + n0]);
            float4 h1 = *reinterpret_cast<const float4*>(&hrow[q * PAD_N + n0 + 4]);
            float4 w0 = *reinterpret_cast<const float4*>(&wbuf[q * PAD_T + t0]);
            float4 w1 = *reinterpret_cast<const float4*>(&wbuf[q * PAD_T + t0 + 4]);
            float hv[8] = {h0.x, h0.y, h0.z, h0.w, h1.x, h1.y, h1.z, h1.w};
            float wv[8] = {w0.x, w0.y, w0.z, w0.w, w1.x, w1.y, w1.z, w1.w};
            #pragma unroll
            for (int i = 0; i < 8; i++) {
                float tmp = a[i] * hv[i];
                #pragma unroll
                for (int j = 0; j < 8; j++)
                    acc[i][j] = fmaf(tmp, wv[j], acc[i][j]);
            }
        }
        __syncthreads();   // all reads of current buffer done

        if (kc + 1 < 512) {
            float* dbuf = sh_w + (buf ^ 1) * BK * PAD_T;
            #pragma unroll
            for (int i = 0; i < 8; i++) {
                int e4 = tid + i * 128;
                int t = e4 >> 3, qw = e4 & 7;
                dbuf[(qw * 4 + 0) * PAD_T + t] = pre[i].x;
                dbuf[(qw * 4 + 1) * PAD_T + t] = pre[i].y;
                dbuf[(qw * 4 + 2) * PAD_T + t] = pre[i].z;
                dbuf[(qw * 4 + 3) * PAD_T + t] = pre[i].w;
            }
            __syncthreads();  // next buffer visible to all
        }
    }

    // Epilogue: act = tanh(val + b_comp); delta = w[s]*(act - tanh(b_comp));
    // scatter-add into out[b, head, t].
    float bc[8], bv[8];
    #pragma unroll
    for (int j = 0; j < 8; j++) {
        bc[j] = b_comp[t0 + j];
        bv[j] = tanhf(bc[j]);
    }

    #pragma unroll
    for (int i = 0; i < 8; i++) {
        int n = nbase + n0 + i;
        int b = n >> 11;            // / S
        int s = n & 2047;           // % S
        int head = heads[n];
        float wgt = w_red[s];
        float* orow = out + ((b << 11) + head) * TDIM;
        #pragma unroll
        for (int j = 0; j < 8; j++) {
            float act = tanhf(acc[i][j] + bc[j]);
            atomicAdd(orow + t0 + j, wgt * (act - bv[j]));
        }
    }
}

// ---------------------------------------------------------------------------
// Launch
// Inputs (metadata order): token_embeddings, dep_embeddings (unused),
// dep_heads, W_comp, b_comp, w_red, b_red
// ---------------------------------------------------------------------------
extern "C" void kernel_launch(void* const* d_in, const int* in_sizes, int n_in,
                              void* d_out, int out_size) {
    const float* tok    = (const float*)d_in[0];
    const int*   heads  = (const int*)  d_in[2];
    const float* W      = (const float*)d_in[3];
    const float* b_comp = (const float*)d_in[4];
    const float* w_red  = (const float*)d_in[5];
    const float* b_red  = (const float*)d_in[6];
    float* out = (float*)d_out;
    (void)in_sizes; (void)n_in; (void)out_size;

    cudaFuncSetAttribute(bilinear_kernel,
                         cudaFuncAttributeMaxDynamicSharedMemorySize, SMEM_BYTES);

    base_kernel<<<1, 128>>>(b_comp, w_red, b_red);
    init_kernel<<<(NTOK * TDIM / 4) / 256, 256>>>(out);
    bilinear_kernel<<<NTOK / BM, 128, SMEM_BYTES>>>(tok, W, heads, w_red, b_comp, out);
}

// round 7
// speedup vs baseline: 1.0004x; 1.0004x over previous
#include <cuda_runtime.h>
#include <math.h>

#define BDIM 8
#define SDIM 2048
#define TDIM 128
#define NTOK (BDIM * SDIM)

#define BM 64
#define BK 32
#define PAD_N 68
#define PAD_T 132
#define SMEM_FLOATS (2 * 128 * PAD_N + 2 * BK * PAD_T)
#define SMEM_BYTES (SMEM_FLOATS * 4)

__device__ float g_base[TDIM];

// ---------------------------------------------------------------------------
// Kernel 1: base[t] = sum(w_red) * tanh(b_comp[t]) + b_red[0]
// ---------------------------------------------------------------------------
__global__ void base_kernel(const float* __restrict__ b_comp,
                            const float* __restrict__ w_red,
                            const float* __restrict__ b_red) {
    __shared__ float red[128];
    int tid = threadIdx.x;
    float s = 0.f;
    for (int i = tid; i < SDIM; i += 128) s += w_red[i];
    red[tid] = s;
    __syncthreads();
    for (int o = 64; o > 0; o >>= 1) {
        if (tid < o) red[tid] += red[tid + o];
        __syncthreads();
    }
    float sw = red[0];
    g_base[tid] = sw * tanhf(b_comp[tid]) + b_red[0];
}

// ---------------------------------------------------------------------------
// Kernel 2: out[b,i,t] = base[t]   (scatter deltas added later via atomics)
// ---------------------------------------------------------------------------
__global__ void init_kernel(float* __restrict__ out) {
    int i = blockIdx.x * blockDim.x + threadIdx.x;   // over NTOK*TDIM/4 float4s
    int t4 = (i & 31) << 2;                          // 32 float4 per T-row
    float4 v = make_float4(g_base[t4], g_base[t4 + 1], g_base[t4 + 2], g_base[t4 + 3]);
    reinterpret_cast<float4*>(out)[i] = v;
}

// ---------------------------------------------------------------------------
// Kernel 3: main bilinear GEMM + tanh epilogue + scatter-add
// C[n,t] = sum_{p,q} token[n,p] * h[n,q] * W[t,p,q],  h = tanh(token)
// Block: 64 tokens x 128 t, 128 threads, 8x8 register tile each.
// K = 16384 = (p,q), streamed as 512 chunks of 32 q (p = chunk>>2).
// ---------------------------------------------------------------------------
__global__ __launch_bounds__(128, 2)
void bilinear_kernel(const float* __restrict__ tok,
                     const float* __restrict__ W,
                     const int* __restrict__ heads,
                     const float* __restrict__ w_red,
                     const float* __restrict__ b_comp,
                     float* __restrict__ out)
{
    extern __shared__ float smem[];
    float* sh_t = smem;                     // [128 p][PAD_N]  token (transposed)
    float* sh_h = smem + 128 * PAD_N;       // [128 q][PAD_N]  tanh(token)
    float* sh_w = smem + 2 * 128 * PAD_N;   // [2][BK q][PAD_T t]

    const int tid = threadIdx.x;
    const int nbase = blockIdx.x * BM;
    const int ng = tid >> 4;                // 0..7  -> 8 tokens
    const int tg = tid & 15;                // 0..15 -> 8 t
    const int n0 = ng << 3;
    const int t0 = tg << 3;

    // Load token tile, build both transposed copies (token and tanh(token)).
    #pragma unroll 4
    for (int e = tid; e < BM * 128; e += 128) {
        int n = e >> 7;
        int p = e & 127;
        float v = tok[(nbase + n) * 128 + p];
        sh_t[p * PAD_N + n] = v;
        sh_h[p * PAD_N + n] = tanhf(v);
    }

    const float4* W4 = reinterpret_cast<const float4*>(W);
    float4 pre[8];

    // Prologue: fetch chunk 0 and stage into buffer 0.
    #pragma unroll
    for (int i = 0; i < 8; i++) {
        int e4 = tid + i * 128;
        int t = e4 >> 3, qw = e4 & 7;
        pre[i] = W4[t * 4096 + qw];          // p=0, qc=0
    }
    #pragma unroll
    for (int i = 0; i < 8; i++) {
        int e4 = tid + i * 128;
        int t = e4 >> 3, qw = e4 & 7;
        sh_w[(qw * 4 + 0) * PAD_T + t] = pre[i].x;
        sh_w[(qw * 4 + 1) * PAD_T + t] = pre[i].y;
        sh_w[(qw * 4 + 2) * PAD_T + t] = pre[i].z;
        sh_w[(qw * 4 + 3) * PAD_T + t] = pre[i].w;
    }
    __syncthreads();

    float acc[8][8];
    #pragma unroll
    for (int i = 0; i < 8; i++)
        #pragma unroll
        for (int j = 0; j < 8; j++) acc[i][j] = 0.f;

    for (int kc = 0; kc < 512; kc++) {
        const int buf = kc & 1;

        // Prefetch next W chunk into registers (overlaps with compute below).
        if (kc + 1 < 512) {
            int pn = (kc + 1) >> 2, qcn = (kc + 1) & 3;
            #pragma unroll
            for (int i = 0; i < 8; i++) {
                int e4 = tid + i * 128;
                int t = e4 >> 3, qw = e4 & 7;
                pre[i] = W4[t * 4096 + pn * 32 + qcn * 8 + qw];
            }
        }

        const int p = kc >> 2, qc = kc & 3;
        float a[8];
        {
            float4 a0 = *reinterpret_cast<const float4*>(&sh_t[p * PAD_N + n0]);
            float4 a1 = *reinterpret_cast<const float4*>(&sh_t[p * PAD_N + n0 + 4]);
            a[0] = a0.x; a[1] = a0.y; a[2] = a0.z; a[3] = a0.w;
            a[4] = a1.x; a[5] = a1.y; a[6] = a1.z; a[7] = a1.w;
        }
        const float* wbuf = sh_w + buf * BK * PAD_T;
        const float* hrow = sh_h + (qc * 32) * PAD_N;

        #pragma unroll 4
        for (int q = 0; q < 32; q++) {
            float4 h0 = *reinterpret_cast<const float4*>(&hrow[q * PAD_N + n0]);
            float4 h1 = *reinterpret_cast<const float4*>(&hrow[q * PAD_N + n0 + 4]);
            float4 w0 = *reinterpret_cast<const float4*>(&wbuf[q * PAD_T + t0]);
            float4 w1 = *reinterpret_cast<const float4*>(&wbuf[q * PAD_T + t0 + 4]);
            float hv[8] = {h0.x, h0.y, h0.z, h0.w, h1.x, h1.y, h1.z, h1.w};
            float wv[8] = {w0.x, w0.y, w0.z, w0.w, w1.x, w1.y, w1.z, w1.w};
            #pragma unroll
            for (int i = 0; i < 8; i++) {
                float tmp = a[i] * hv[i];
                #pragma unroll
                for (int j = 0; j < 8; j++)
                    acc[i][j] = fmaf(tmp, wv[j], acc[i][j]);
            }
        }
        __syncthreads();   // all reads of current buffer done

        if (kc + 1 < 512) {
            float* dbuf = sh_w + (buf ^ 1) * BK * PAD_T;
            #pragma unroll
            for (int i = 0; i < 8; i++) {
                int e4 = tid + i * 128;
                int t = e4 >> 3, qw = e4 & 7;
                dbuf[(qw * 4 + 0) * PAD_T + t] = pre[i].x;
                dbuf[(qw * 4 + 1) * PAD_T + t] = pre[i].y;
                dbuf[(qw * 4 + 2) * PAD_T + t] = pre[i].z;
                dbuf[(qw * 4 + 3) * PAD_T + t] = pre[i].w;
            }
            __syncthreads();  // next buffer visible to all
        }
    }

    // Epilogue: act = tanh(val + b_comp); delta = w[s]*(act - tanh(b_comp));
    // scatter-add into out[b, head, t].
    float bc[8], bv[8];
    #pragma unroll
    for (int j = 0; j < 8; j++) {
        bc[j] = b_comp[t0 + j];
        bv[j] = tanhf(bc[j]);
    }

    #pragma unroll
    for (int i = 0; i < 8; i++) {
        int n = nbase + n0 + i;
        int b = n >> 11;            // / S
        int s = n & 2047;           // % S
        int head = heads[n];
        float wgt = w_red[s];
        float* orow = out + ((b << 11) + head) * TDIM;
        #pragma unroll
        for (int j = 0; j < 8; j++) {
            float act = tanhf(acc[i][j] + bc[j]);
            atomicAdd(orow + t0 + j, wgt * (act - bv[j]));
        }
    }
}

// ---------------------------------------------------------------------------
// Launch
// Inputs (metadata order): token_embeddings, dep_embeddings (unused),
// dep_heads, W_comp, b_comp, w_red, b_red
// ---------------------------------------------------------------------------
extern "C" void kernel_launch(void* const* d_in, const int* in_sizes, int n_in,
                              void* d_out, int out_size) {
    const float* tok    = (const float*)d_in[0];
    const int*   heads  = (const int*)  d_in[2];
    const float* W      = (const float*)d_in[3];
    const float* b_comp = (const float*)d_in[4];
    const float* w_red  = (const float*)d_in[5];
    const float* b_red  = (const float*)d_in[6];
    float* out = (float*)d_out;
    (void)in_sizes; (void)n_in; (void)out_size;

    cudaFuncSetAttribute(bilinear_kernel,
                         cudaFuncAttributeMaxDynamicSharedMemorySize, SMEM_BYTES);

    base_kernel<<<1, 128>>>(b_comp, w_red, b_red);
    init_kernel<<<(NTOK * TDIM / 4) / 256, 256>>>(out);
    bilinear_kernel<<<NTOK / BM, 128, SMEM_BYTES>>>(tok, W, heads, w_red, b_comp, out);
}

// round 11
// speedup vs baseline: 2.8553x; 2.8543x over previous
#include <cuda_runtime.h>
#include <math.h>
#include <stdint.h>

#define SDIM 2048
#define TDIM 128
#define NTOK 16384
#define NCHUNK 512          // K = 16384 in chunks of 32

// SMEM byte offsets (dynamic)
#define SM_BC 0
#define SM_BV 512
#define SM_H  1024                       // h tile [n][q] 128x128 f32, swizzled
#define SM_TS (SM_H + 65536)             // tok transposed [p][n] 128x128 f32
#define SM_W  (SM_TS + 65536)            // 4 stages x 16KB, swizzled
#define SMEM_BYTES (SM_W + 4 * 16384)    // 197632

__device__ __forceinline__ uint32_t smem_u32(const void* p) {
    uint32_t a;
    asm("{ .reg .u64 t; cvta.to.shared.u64 t, %1; cvt.u32.u64 %0, t; }" : "=r"(a) : "l"(p));
    return a;
}
__device__ __forceinline__ void cp16(uint32_t s, const void* g) {
    asm volatile("cp.async.cg.shared.global [%0], [%1], 16;" :: "r"(s), "l"(g) : "memory");
}
#define CP_COMMIT() asm volatile("cp.async.commit_group;" ::: "memory")
#define CP_WAIT(n)  asm volatile("cp.async.wait_group %0;" :: "n"(n) : "memory")

__device__ __forceinline__ void ldm4(uint32_t* r, uint32_t a) {
    asm volatile("ldmatrix.sync.aligned.m8n8.x4.shared.b16 {%0,%1,%2,%3}, [%4];"
        : "=r"(r[0]), "=r"(r[1]), "=r"(r[2]), "=r"(r[3]) : "r"(a));
}
__device__ __forceinline__ uint32_t cvt_tf32(float x) {
    uint32_t r; asm("cvt.rna.tf32.f32 %0, %1;" : "=r"(r) : "f"(x)); return r;
}
__device__ __forceinline__ void mma8(float* d, const uint32_t* a, uint32_t b0, uint32_t b1) {
    asm volatile("mma.sync.aligned.m16n8k8.row.col.f32.tf32.tf32.f32 "
        "{%0,%1,%2,%3}, {%4,%5,%6,%7}, {%8,%9}, {%0,%1,%2,%3};"
        : "+f"(d[0]), "+f"(d[1]), "+f"(d[2]), "+f"(d[3])
        : "r"(a[0]), "r"(a[1]), "r"(a[2]), "r"(a[3]), "r"(b0), "r"(b1));
}

// ---------------------------------------------------------------------------
// init: out[b,i,t] = sum(w_red)*tanh(b_comp[t]) + b_red
// ---------------------------------------------------------------------------
__global__ void init_kernel(const float* __restrict__ b_comp,
                            const float* __restrict__ w_red,
                            const float* __restrict__ b_red,
                            float* __restrict__ out) {
    __shared__ float base_s[128];
    __shared__ float ws[8];
    int tid = threadIdx.x;  // 256
    float s = 0.f;
    #pragma unroll
    for (int i = 0; i < 8; i++) s += w_red[tid + i * 256];
    #pragma unroll
    for (int o = 16; o > 0; o >>= 1) s += __shfl_xor_sync(0xFFFFFFFFu, s, o);
    if ((tid & 31) == 0) ws[tid >> 5] = s;
    __syncthreads();
    if (tid < 128) {
        float sw = ws[0] + ws[1] + ws[2] + ws[3] + ws[4] + ws[5] + ws[6] + ws[7];
        base_s[tid] = sw * tanhf(b_comp[tid]) + b_red[0];
    }
    __syncthreads();
    int i = blockIdx.x * 256 + tid;
    float4 v = *reinterpret_cast<const float4*>(&base_s[(i & 31) << 2]);
    reinterpret_cast<float4*>(out)[i] = v;
}

// ---------------------------------------------------------------------------
// Main: mma.sync tf32 GEMM. C[128 tok x 128 t], K=16384=(p,q).
// 4 warps in 2x2, warp tile 64x64. A frags = tok[n,p]*h[n,q] built in regs.
// ---------------------------------------------------------------------------
__global__ __launch_bounds__(128, 1)
void bilinear_mma(const float* __restrict__ tok,
                  const int* __restrict__ heads,
                  const float* __restrict__ W,
                  const float* __restrict__ b_comp,
                  const float* __restrict__ w_red,
                  float* __restrict__ out)
{
    extern __shared__ __align__(1024) char smem[];
    const uint32_t sb = smem_u32(smem);
    const int tid  = threadIdx.x;
    const int lane = tid & 31;
    const int warp = tid >> 5;
    const int wr = warp >> 1, wc = warp & 1;       // 2x2 warp grid
    const int tl = lane >> 3, lr = lane & 7;       // ldmatrix tile / row
    const int grp = lane >> 2, tig = lane & 3;     // mma frag row / col groups
    const int nbase = blockIdx.x * 128;

    // --- cp.async prologue: W chunks 0..2 into stages 0..2 ---
    const uint32_t wsw = (uint32_t)(tid & 7) << 4;
    #pragma unroll
    for (int c = 0; c < 3; c++) {
        const char* src = (const char*)W + ((size_t)tid * 16384 + (size_t)c * 32) * 4;
        uint32_t dst = sb + SM_W + (uint32_t)c * 16384 + (uint32_t)tid * 128;
        #pragma unroll
        for (int j = 0; j < 8; j++) cp16(dst + (((uint32_t)j * 16) ^ wsw), src + j * 16);
        CP_COMMIT();
    }

    // --- build h (swizzled [n][q]) and ts ([p][n]) tiles; bc/bv ---
    {
        const float4* t4 = reinterpret_cast<const float4*>(tok + (size_t)(nbase + tid) * TDIM);
        #pragma unroll
        for (int j = 0; j < 32; j++) {
            float4 v = t4[j];
            float4 hv = make_float4(tanhf(v.x), tanhf(v.y), tanhf(v.z), tanhf(v.w));
            *reinterpret_cast<float4*>(smem + SM_H + tid * 512 + (((uint32_t)j * 16) ^ wsw)) = hv;
            float* ts = (float*)(smem + SM_TS);
            ts[(4 * j + 0) * 128 + tid] = v.x;
            ts[(4 * j + 1) * 128 + tid] = v.y;
            ts[(4 * j + 2) * 128 + tid] = v.z;
            ts[(4 * j + 3) * 128 + tid] = v.w;
        }
        float bcv = b_comp[tid];
        ((float*)(smem + SM_BC))[tid] = bcv;
        ((float*)(smem + SM_BV))[tid] = tanhf(bcv);
    }
    __syncthreads();

    // per-thread ldmatrix address bases (swizzle XOR is constant: row&7 == lr)
    const uint32_t swz = (uint32_t)lr << 4;
    const uint32_t aA_base = sb + SM_H + (uint32_t)(wr * 64 + (tl & 1) * 8 + lr) * 512;
    const uint32_t colA_off = (uint32_t)(tl >> 1) * 16;
    const uint32_t bB_off = (uint32_t)(wc * 64 + (tl >> 1) * 8 + lr) * 128;
    const uint32_t colB_off = (uint32_t)(tl & 1) * 16;
    const float* ts = (const float*)(smem + SM_TS);

    float d[4][8][4];
    #pragma unroll
    for (int i = 0; i < 4; i++)
        #pragma unroll
        for (int g = 0; g < 8; g++)
            #pragma unroll
            for (int e = 0; e < 4; e++) d[i][g][e] = 0.f;

    float tk[4][2];

    #pragma unroll 1
    for (int c = 0; c < NCHUNK; c++) {
        if (c < NCHUNK - 2)      { CP_WAIT(2); }
        else if (c == NCHUNK - 2){ CP_WAIT(1); }
        else                     { CP_WAIT(0); }
        __syncthreads();

        // prefetch chunk c+3 into stage (c+3)&3 (stage of c-1, fully consumed)
        if (c + 3 < NCHUNK) {
            const int c2 = c + 3;
            const char* src = (const char*)W + ((size_t)tid * 16384 + (size_t)c2 * 32) * 4;
            uint32_t dst = sb + SM_W + (uint32_t)(c2 & 3) * 16384 + (uint32_t)tid * 128;
            #pragma unroll
            for (int j = 0; j < 8; j++) cp16(dst + (((uint32_t)j * 16) ^ wsw), src + j * 16);
            CP_COMMIT();
        }

        const int p = c >> 2, qc = c & 3;
        if (qc == 0) {
            #pragma unroll
            for (int i = 0; i < 4; i++) {
                tk[i][0] = ts[p * 128 + wr * 64 + i * 16 + grp];
                tk[i][1] = ts[p * 128 + wr * 64 + i * 16 + 8 + grp];
            }
        }
        const uint32_t wst = sb + SM_W + (uint32_t)(c & 3) * 16384 + bB_off;

        #pragma unroll
        for (int ks = 0; ks < 4; ks++) {
            uint32_t af[4][4], bf[4][4];
            const uint32_t colA = (uint32_t)(qc * 128 + ks * 32) + colA_off;
            #pragma unroll
            for (int i = 0; i < 4; i++)
                ldm4(af[i], aA_base + (uint32_t)i * 8192 + (colA ^ swz));
            const uint32_t colB = (uint32_t)(ks * 32) + colB_off;
            #pragma unroll
            for (int gp = 0; gp < 4; gp++)
                ldm4(bf[gp], wst + (uint32_t)gp * 2048 + (colB ^ swz));

            // A frag: a = cvt_tf32(tok_scalar * h);  B frag: cvt_tf32(W)
            #pragma unroll
            for (int i = 0; i < 4; i++) {
                af[i][0] = cvt_tf32(tk[i][0] * __uint_as_float(af[i][0]));
                af[i][1] = cvt_tf32(tk[i][1] * __uint_as_float(af[i][1]));
                af[i][2] = cvt_tf32(tk[i][0] * __uint_as_float(af[i][2]));
                af[i][3] = cvt_tf32(tk[i][1] * __uint_as_float(af[i][3]));
            }
            #pragma unroll
            for (int gp = 0; gp < 4; gp++)
                #pragma unroll
                for (int e = 0; e < 4; e++)
                    bf[gp][e] = cvt_tf32(__uint_as_float(bf[gp][e]));

            #pragma unroll
            for (int i = 0; i < 4; i++)
                #pragma unroll
                for (int gp = 0; gp < 4; gp++) {
                    mma8(d[i][2 * gp + 0], af[i], bf[gp][0], bf[gp][1]);
                    mma8(d[i][2 * gp + 1], af[i], bf[gp][2], bf[gp][3]);
                }
        }
    }

    // --- epilogue: act = tanh(val + bc); atomicAdd(w_red[s]*(act - bv)) ---
    const int b = nbase >> 11;
    const float* bcS = (const float*)(smem + SM_BC);
    const float* bvS = (const float*)(smem + SM_BV);
    #pragma unroll
    for (int i = 0; i < 4; i++) {
        #pragma unroll
        for (int half = 0; half < 2; half++) {
            const int nl = wr * 64 + i * 16 + half * 8 + grp;
            const int n = nbase + nl;
            const int head = heads[n];
            const float wgt = w_red[n & 2047];
            float* orow = out + ((size_t)((b << 11) + head)) * TDIM;
            #pragma unroll
            for (int g = 0; g < 8; g++) {
                const int col = wc * 64 + g * 8 + tig * 2;
                float v0 = d[i][g][half * 2 + 0];
                float v1 = d[i][g][half * 2 + 1];
                atomicAdd(orow + col,     wgt * (tanhf(v0 + bcS[col])     - bvS[col]));
                atomicAdd(orow + col + 1, wgt * (tanhf(v1 + bcS[col + 1]) - bvS[col + 1]));
            }
        }
    }
}

// ---------------------------------------------------------------------------
// Inputs: token, dep(unused), heads, W_comp, b_comp, w_red, b_red
// ---------------------------------------------------------------------------
extern "C" void kernel_launch(void* const* d_in, const int* in_sizes, int n_in,
                              void* d_out, int out_size) {
    const float* tok    = (const float*)d_in[0];
    const int*   heads  = (const int*)  d_in[2];
    const float* W      = (const float*)d_in[3];
    const float* b_comp = (const float*)d_in[4];
    const float* w_red  = (const float*)d_in[5];
    const float* b_red  = (const float*)d_in[6];
    float* out = (float*)d_out;
    (void)in_sizes; (void)n_in; (void)out_size;

    cudaFuncSetAttribute(bilinear_mma,
                         cudaFuncAttributeMaxDynamicSharedMemorySize, SMEM_BYTES);

    init_kernel<<<NTOK * TDIM / 4 / 256, 256>>>(b_comp, w_red, b_red, out);
    bilinear_mma<<<NTOK / 128, 128, SMEM_BYTES>>>(tok, heads, W, b_comp, w_red, out);
}

// round 15
// speedup vs baseline: 3.1368x; 1.0986x over previous
#include <cuda_runtime.h>
#include <math.h>
#include <stdint.h>

#define SDIM 2048
#define TDIM 128
#define NTOK 16384
#define NCHUNK 512          // K = 16384 in chunks of 32

// SMEM byte offsets (dynamic)
#define SM_BC 0
#define SM_BV 512
#define SM_H  1024                       // h tile [n][q] 128x128 f32, swizzled
#define SM_TS (SM_H + 65536)             // tok transposed [p][n] 128x128 f32
#define SM_W  (SM_TS + 65536)            // 4 stages x 16KB, swizzled
#define SMEM_BYTES (SM_W + 4 * 16384)    // 197632

__device__ __forceinline__ uint32_t smem_u32(const void* p) {
    uint32_t a;
    asm("{ .reg .u64 t; cvta.to.shared.u64 t, %1; cvt.u32.u64 %0, t; }" : "=r"(a) : "l"(p));
    return a;
}
__device__ __forceinline__ void cp16(uint32_t s, const void* g) {
    asm volatile("cp.async.cg.shared.global [%0], [%1], 16;" :: "r"(s), "l"(g) : "memory");
}
#define CP_COMMIT() asm volatile("cp.async.commit_group;" ::: "memory")
#define CP_WAIT(n)  asm volatile("cp.async.wait_group %0;" :: "n"(n) : "memory")

__device__ __forceinline__ void ldm4(uint32_t* r, uint32_t a) {
    asm volatile("ldmatrix.sync.aligned.m8n8.x4.shared.b16 {%0,%1,%2,%3}, [%4];"
        : "=r"(r[0]), "=r"(r[1]), "=r"(r[2]), "=r"(r[3]) : "r"(a));
}
__device__ __forceinline__ uint32_t cvt_tf32(float x) {
    uint32_t r; asm("cvt.rna.tf32.f32 %0, %1;" : "=r"(r) : "f"(x)); return r;
}
__device__ __forceinline__ void mma8(float* d, const uint32_t* a, uint32_t b0, uint32_t b1) {
    asm volatile("mma.sync.aligned.m16n8k8.row.col.f32.tf32.tf32.f32 "
        "{%0,%1,%2,%3}, {%4,%5,%6,%7}, {%8,%9}, {%0,%1,%2,%3};"
        : "+f"(d[0]), "+f"(d[1]), "+f"(d[2]), "+f"(d[3])
        : "r"(a[0]), "r"(a[1]), "r"(a[2]), "r"(a[3]), "r"(b0), "r"(b1));
}

// ---------------------------------------------------------------------------
// init: out[b,i,t] = sum(w_red)*tanh(b_comp[t]) + b_red
// ---------------------------------------------------------------------------
__global__ void init_kernel(const float* __restrict__ b_comp,
                            const float* __restrict__ w_red,
                            const float* __restrict__ b_red,
                            float* __restrict__ out) {
    __shared__ float base_s[128];
    __shared__ float ws[8];
    int tid = threadIdx.x;  // 256
    float s = 0.f;
    #pragma unroll
    for (int i = 0; i < 8; i++) s += w_red[tid + i * 256];
    #pragma unroll
    for (int o = 16; o > 0; o >>= 1) s += __shfl_xor_sync(0xFFFFFFFFu, s, o);
    if ((tid & 31) == 0) ws[tid >> 5] = s;
    __syncthreads();
    if (tid < 128) {
        float sw = ws[0] + ws[1] + ws[2] + ws[3] + ws[4] + ws[5] + ws[6] + ws[7];
        base_s[tid] = sw * tanhf(b_comp[tid]) + b_red[0];
    }
    __syncthreads();
    int i = blockIdx.x * 256 + tid;
    float4 v = *reinterpret_cast<const float4*>(&base_s[(i & 31) << 2]);
    reinterpret_cast<float4*>(out)[i] = v;
}

// ---------------------------------------------------------------------------
// Main: mma.sync tf32 GEMM. C[128 tok x 128 t], K=16384=(p,q).
// 256 threads, 8 warps in 2x4 grid, warp tile 64x32.
// A frags = tok[n,p]*h[n,q] built in regs from static SMEM tiles.
// ---------------------------------------------------------------------------
__global__ __launch_bounds__(256, 1)
void bilinear_mma(const float* __restrict__ tok,
                  const int* __restrict__ heads,
                  const float* __restrict__ W,
                  const float* __restrict__ b_comp,
                  const float* __restrict__ w_red,
                  float* __restrict__ out)
{
    extern __shared__ __align__(1024) char smem[];
    const uint32_t sb = smem_u32(smem);
    const int tid  = threadIdx.x;
    const int lane = tid & 31;
    const int warp = tid >> 5;
    const int wr = warp >> 2, wc = warp & 3;       // 2x4 warp grid
    const int tl = lane >> 3, lr = lane & 7;       // ldmatrix tile / row
    const int grp = lane >> 2, tig = lane & 3;     // mma frag row / col groups
    const int nbase = blockIdx.x * 128;

    // --- cp.async prologue: W chunks 0..2 (each thread: 1 row-half = 4x16B)
    const int wrow = tid >> 1;                     // 0..127 (t row)
    const int wjb  = (tid & 1) * 4;                // granule base
    const uint32_t wsw = ((uint32_t)wrow & 7) << 4;
    #pragma unroll
    for (int c = 0; c < 3; c++) {
        const char* src = (const char*)W + ((size_t)wrow * 16384 + (size_t)c * 32) * 4 + (size_t)wjb * 16;
        uint32_t dst = sb + SM_W + (uint32_t)c * 16384 + (uint32_t)wrow * 128;
        #pragma unroll
        for (int j = 0; j < 4; j++)
            cp16(dst + ((((uint32_t)(wjb + j)) * 16) ^ wsw), src + j * 16);
        CP_COMMIT();
    }

    // --- build h (swizzled [n][q]) and ts ([p][n]); each thread: half a row
    {
        const int r = tid >> 1, half = tid & 1;
        const uint32_t rsw = ((uint32_t)r & 7) << 4;
        const float4* t4 = reinterpret_cast<const float4*>(
            tok + (size_t)(nbase + r) * TDIM + (size_t)half * 64);
        float* ts = (float*)(smem + SM_TS);
        #pragma unroll
        for (int j = 0; j < 16; j++) {
            const int col4 = half * 16 + j;
            float4 v = t4[j];
            float4 hv = make_float4(tanhf(v.x), tanhf(v.y), tanhf(v.z), tanhf(v.w));
            *reinterpret_cast<float4*>(smem + SM_H + r * 512 + ((((uint32_t)col4) * 16) ^ rsw)) = hv;
            ts[(4 * col4 + 0) * 128 + r] = v.x;
            ts[(4 * col4 + 1) * 128 + r] = v.y;
            ts[(4 * col4 + 2) * 128 + r] = v.z;
            ts[(4 * col4 + 3) * 128 + r] = v.w;
        }
        if (tid < 128) {
            float bcv = b_comp[tid];
            ((float*)(smem + SM_BC))[tid] = bcv;
            ((float*)(smem + SM_BV))[tid] = tanhf(bcv);
        }
    }
    __syncthreads();

    // per-thread ldmatrix bases (swizzle XOR constant: row&7 == lr)
    const uint32_t swz = (uint32_t)lr << 4;
    const uint32_t aA_base = sb + SM_H + (uint32_t)(wr * 64 + (tl & 1) * 8 + lr) * 512;
    const uint32_t colA_off = (uint32_t)(tl >> 1) * 16;
    const uint32_t bB_off = (uint32_t)(wc * 32 + (tl >> 1) * 8 + lr) * 128;
    const uint32_t colB_off = (uint32_t)(tl & 1) * 16;
    const float* ts = (const float*)(smem + SM_TS);

    float d[4][4][4];
    #pragma unroll
    for (int i = 0; i < 4; i++)
        #pragma unroll
        for (int g = 0; g < 4; g++)
            #pragma unroll
            for (int e = 0; e < 4; e++) d[i][g][e] = 0.f;

    float tk[4][2];

    #pragma unroll 1
    for (int c = 0; c < NCHUNK; c++) {
        if (c < NCHUNK - 2)      { CP_WAIT(2); }
        else if (c == NCHUNK - 2){ CP_WAIT(1); }
        else                     { CP_WAIT(0); }
        __syncthreads();

        // prefetch chunk c+3 into stage (c+3)&3 (stage of c-1, fully consumed)
        if (c + 3 < NCHUNK) {
            const int c2 = c + 3;
            const char* src = (const char*)W + ((size_t)wrow * 16384 + (size_t)c2 * 32) * 4 + (size_t)wjb * 16;
            uint32_t dst = sb + SM_W + (uint32_t)(c2 & 3) * 16384 + (uint32_t)wrow * 128;
            #pragma unroll
            for (int j = 0; j < 4; j++)
                cp16(dst + ((((uint32_t)(wjb + j)) * 16) ^ wsw), src + j * 16);
            CP_COMMIT();
        }

        const int p = c >> 2, qc = c & 3;
        if (qc == 0) {
            #pragma unroll
            for (int i = 0; i < 4; i++) {
                tk[i][0] = ts[p * 128 + wr * 64 + i * 16 + grp];
                tk[i][1] = ts[p * 128 + wr * 64 + i * 16 + 8 + grp];
            }
        }
        const uint32_t wst = sb + SM_W + (uint32_t)(c & 3) * 16384 + bB_off;

        #pragma unroll
        for (int ks = 0; ks < 4; ks++) {
            uint32_t af[4][4], bf[2][4];
            const uint32_t colA = (uint32_t)(qc * 128 + ks * 32) + colA_off;
            #pragma unroll
            for (int i = 0; i < 4; i++)
                ldm4(af[i], aA_base + (uint32_t)i * 8192 + (colA ^ swz));
            const uint32_t colB = (uint32_t)(ks * 32) + colB_off;
            #pragma unroll
            for (int gp = 0; gp < 2; gp++)
                ldm4(bf[gp], wst + (uint32_t)gp * 2048 + (colB ^ swz));

            // A frag: a = cvt_tf32(tok_scalar * h);  B frag: cvt_tf32(W)
            #pragma unroll
            for (int i = 0; i < 4; i++) {
                af[i][0] = cvt_tf32(tk[i][0] * __uint_as_float(af[i][0]));
                af[i][1] = cvt_tf32(tk[i][1] * __uint_as_float(af[i][1]));
                af[i][2] = cvt_tf32(tk[i][0] * __uint_as_float(af[i][2]));
                af[i][3] = cvt_tf32(tk[i][1] * __uint_as_float(af[i][3]));
            }
            #pragma unroll
            for (int gp = 0; gp < 2; gp++)
                #pragma unroll
                for (int e = 0; e < 4; e++)
                    bf[gp][e] = cvt_tf32(__uint_as_float(bf[gp][e]));

            #pragma unroll
            for (int i = 0; i < 4; i++)
                #pragma unroll
                for (int gp = 0; gp < 2; gp++) {
                    mma8(d[i][2 * gp + 0], af[i], bf[gp][0], bf[gp][1]);
                    mma8(d[i][2 * gp + 1], af[i], bf[gp][2], bf[gp][3]);
                }
        }
    }

    // --- epilogue: act = tanh(val + bc); atomicAdd(w_red[s]*(act - bv)) ---
    const int b = nbase >> 11;
    const float* bcS = (const float*)(smem + SM_BC);
    const float* bvS = (const float*)(smem + SM_BV);
    #pragma unroll
    for (int i = 0; i < 4; i++) {
        #pragma unroll
        for (int half = 0; half < 2; half++) {
            const int nl = wr * 64 + i * 16 + half * 8 + grp;
            const int n = nbase + nl;
            const int head = heads[n];
            const float wgt = w_red[n & 2047];
            float* orow = out + ((size_t)((b << 11) + head)) * TDIM;
            #pragma unroll
            for (int g = 0; g < 4; g++) {
                const int col = wc * 32 + g * 8 + tig * 2;
                float v0 = d[i][g][half * 2 + 0];
                float v1 = d[i][g][half * 2 + 1];
                atomicAdd(orow + col,     wgt * (tanhf(v0 + bcS[col])     - bvS[col]));
                atomicAdd(orow + col + 1, wgt * (tanhf(v1 + bcS[col + 1]) - bvS[col + 1]));
            }
        }
    }
}

// ---------------------------------------------------------------------------
// Inputs: token, dep(unused), heads, W_comp, b_comp, w_red, b_red
// ---------------------------------------------------------------------------
extern "C" void kernel_launch(void* const* d_in, const int* in_sizes, int n_in,
                              void* d_out, int out_size) {
    const float* tok    = (const float*)d_in[0];
    const int*   heads  = (const int*)  d_in[2];
    const float* W      = (const float*)d_in[3];
    const float* b_comp = (const float*)d_in[4];
    const float* w_red  = (const float*)d_in[5];
    const float* b_red  = (const float*)d_in[6];
    float* out = (float*)d_out;
    (void)in_sizes; (void)n_in; (void)out_size;

    cudaFuncSetAttribute(bilinear_mma,
                         cudaFuncAttributeMaxDynamicSharedMemorySize, SMEM_BYTES);

    init_kernel<<<NTOK * TDIM / 4 / 256, 256>>>(b_comp, w_red, b_red, out);
    bilinear_mma<<<NTOK / 128, 256, SMEM_BYTES>>>(tok, heads, W, b_comp, w_red, out);
}